// round 16
// baseline (speedup 1.0000x reference)
#include <cuda_runtime.h>
#include <cstdint>

// CondFilterT: per row b (BATCH=16384):
//   e = table[inp[b,0]]  (64 fp32)   -> out[b, 0:64] raw
//   for c in 0..49: v = table[inp[b,1+c]]
//     filtered = v * dot(e,v) / (||e|| * ||v||^2)  -> out[b, 64+64c : 64+64(c+1)]
//
// R15: R13's best-kernel config (half-warp rows, U=5 double buffer, 5 gather
// lines in flight) with the copy overhead removed:
//  - PING-PONG buffers via unroll-2 (alternate A/B roles) -> zero rotation
//    MOVs (R13/R14 spent 10-16% of issue on alu, largely buffer copies).
//  - PROLOGUE OVERLAP: first batch's 5 gathers issued before the event-norm
//    shuffle reduction, so the reduction chain hides their L2 latency.
// 50 conds = 10 batches of 5 = 5 unrolled pairs, no tail.

#define CF_BATCH  16384
#define CF_NCONDS 50
#define CF_EMB    64
#define CF_ROWLEN (CF_EMB * (1 + CF_NCONDS))   // 3264 floats per output row

#define ROWS_PER_BLOCK 8                        // 4 warps x 2 rows
#define IDX_PITCH 52

__global__ __launch_bounds__(128, 7)
void condfilter_kernel(const int* __restrict__ inp,
                       const float* __restrict__ table,
                       float* __restrict__ out)
{
    const unsigned FULL = 0xFFFFFFFFu;
    __shared__ int sidx[ROWS_PER_BLOCK][IDX_PITCH];

    const int tid = threadIdx.x;

    // ---- cooperative coalesced load of this block's 8x51 indices ----
    {
        const int* gsrc = inp + (size_t)blockIdx.x * ROWS_PER_BLOCK * (1 + CF_NCONDS);
        for (int i = tid; i < ROWS_PER_BLOCK * (1 + CF_NCONDS); i += 128)
            sidx[i / (1 + CF_NCONDS)][i % (1 + CF_NCONDS)] = gsrc[i];
    }
    __syncthreads();

    const int hl    = tid & 15;                 // lane within half-warp
    const int rib   = tid >> 4;                 // row within block (0..7)
    const int rowid = blockIdx.x * ROWS_PER_BLOCK + rib;
    const int* __restrict__ myidx = &sidx[rib][0];

    const float4* __restrict__ tab = (const float4*)table;   // 16 float4 / row

    auto load5 = [&](float4* b, int c0) {
        #pragma unroll
        for (int u = 0; u < 5; u++)
            b[u] = __ldg(tab + (size_t)myidx[1 + c0 + u] * (CF_EMB / 4) + hl);
    };

    // ---- prologue: event load + FIRST BATCH loads, then event reduction ----
    const int e_idx = myidx[0];                 // broadcast LDS
    const float4 e = __ldg(tab + (size_t)e_idx * (CF_EMB / 4) + hl);

    float4 A[5], B[5];
    load5(A, 0);                                // batch 0 in flight early

    float ss = e.x * e.x + e.y * e.y + e.z * e.z + e.w * e.w;
    #pragma unroll
    for (int o = 8; o > 0; o >>= 1) ss += __shfl_xor_sync(FULL, ss, o);
    const float e_inv = rsqrtf(ss);

    float4* orow = (float4*)(out + (size_t)rowid * CF_ROWLEN);
    __stcs(orow + hl, e);   // raw event embedding, 256B coalesced, evict-first

    // ---- reduce + scale + store one batch of 5 conditions ----
    auto process = [&](const float4* v, int c0) {
        float s1[5], s2[5];
        #pragma unroll
        for (int u = 0; u < 5; u++) {
            s1[u] = v[u].x * v[u].x + v[u].y * v[u].y
                  + v[u].z * v[u].z + v[u].w * v[u].w;      // ||v||^2
            s2[u] = e.x * v[u].x + e.y * v[u].y
                  + e.z * v[u].z + e.w * v[u].w;            // dot(e,v)
        }
        #pragma unroll
        for (int o = 8; o > 0; o >>= 1) {
            #pragma unroll
            for (int u = 0; u < 5; u++) {
                s1[u] += __shfl_xor_sync(FULL, s1[u], o);
                s2[u] += __shfl_xor_sync(FULL, s2[u], o);
            }
        }
        #pragma unroll
        for (int u = 0; u < 5; u++) {
            const float sc = __fdividef(s2[u] * e_inv, s1[u]);   // score/||v||
            float4 w;
            w.x = v[u].x * sc;
            w.y = v[u].y * sc;
            w.z = v[u].z * sc;
            w.w = v[u].w * sc;
            __stcs(orow + 16 + (size_t)(c0 + u) * 16 + hl, w);   // coalesced
        }
    };

    // ---- ping-pong pipelined loop: 5 pairs, no copies, no tail ----
    // pair i: prefetch batch 2i+1 into B, process A (batch 2i),
    //         prefetch batch 2i+2 into A (except last), process B (batch 2i+1)
    #pragma unroll 1
    for (int i = 0; i < 5; i++) {
        const int c0 = i * 10;
        load5(B, c0 + 5);
        process(A, c0);
        if (i < 4) load5(A, c0 + 10);
        process(B, c0 + 5);
    }
}

extern "C" void kernel_launch(void* const* d_in, const int* in_sizes, int n_in,
                              void* d_out, int out_size)
{
    const int*   inp   = (const int*)d_in[0];     // (16384, 51) int32
    const float* table = (const float*)d_in[1];   // (100002, 64) float32
    float*       out   = (float*)d_out;           // (16384, 3264) float32

    const int grid = CF_BATCH / ROWS_PER_BLOCK;   // 2048 (exact)
    condfilter_kernel<<<grid, 128>>>(inp, table, out);
}